// round 5
// baseline (speedup 1.0000x reference)
#include <cuda_runtime.h>
#include <cuda_fp16.h>
#include <cstdint>

#define BATCH   64
#define SEQ     1024
#define IDIM    128
#define HDIM    512
#define G4      2048
#define KTOT    640
#define NGRP    4
#define GB      16
#define NCTA    32
#define HC      16
#define NL      64
#define THREADS 128
#define NCH_H   32
#define NCH_X   8

#define ZSTR    648
#define OFF_Z   0
#define OFF_AW  (NL * ZSTR * 2)          // 82944
#define AWSZ    (NCH_H * 512)            // 16 KB per-warp staging
#define SMEM_SZ (OFF_AW + 4 * AWSZ)      // 148480 B

// ---- global scratch (static) -------------------------------------------------
__device__ uint32_t g_xfrag[(size_t)NGRP * SEQ * NCH_X * 128];  // 16 MB, frag layout
__device__ uint32_t g_hfrag[2 * NGRP * NCTA * 128];             // ping-pong h chunks
__device__ float    g_hfin[BATCH][HDIM];                        // exact final h
__device__ int      g_flag[NGRP][NCTA][32];                     // 128B-padded flags
__device__ int      g_done[NGRP][NCTA];
__device__ int      g_cnt, g_gen;

// ---- prologue-only global barrier (replay-safe) ------------------------------
__device__ __forceinline__ void bar_all(int n)
{
    int my;
    asm volatile("ld.acquire.gpu.global.b32 %0, [%1];" : "=r"(my) : "l"(&g_gen));
    __threadfence();
    if (atomicAdd(&g_cnt, 1) == n - 1) {
        atomicExch(&g_cnt, 0);
        __threadfence();
        atomicAdd(&g_gen, 1);
    } else {
        int v;
        do { asm volatile("ld.acquire.gpu.global.b32 %0, [%1];" : "=r"(v) : "l"(&g_gen)); }
        while (v == my);
    }
}

// warp-parallel poll: lane l watches producer l's flag
__device__ __forceinline__ void poll_flags(int grp, int lane, int need)
{
    const int* fp = &g_flag[grp][lane][0];
    int v;
    do { asm volatile("ld.acquire.gpu.global.b32 %0, [%1];" : "=r"(v) : "l"(fp)); }
    while (__any_sync(0xffffffffu, v < need));
}

__device__ __forceinline__ int atom_add_acqrel(int* p, int v)
{
    int old;
    asm volatile("atom.add.acq_rel.gpu.global.s32 %0, [%1], %2;"
                 : "=r"(old) : "l"(p), "r"(v) : "memory");
    return old;
}

__device__ __forceinline__ void cpasync16(uint32_t dst, const void* src)
{
    asm volatile("cp.async.cg.shared.global [%0], [%1], 16;" :: "r"(dst), "l"(src));
}
__device__ __forceinline__ void cpwait()
{
    asm volatile("cp.async.wait_all;" ::: "memory");
}

__device__ __forceinline__ void lds128(unsigned r[4], uint32_t a)
{
    asm volatile("ld.shared.v4.b32 {%0,%1,%2,%3}, [%4];"
                 : "=r"(r[0]), "=r"(r[1]), "=r"(r[2]), "=r"(r[3]) : "r"(a));
}
__device__ __forceinline__ void ldsm4(unsigned r[4], uint32_t a)
{
    asm volatile("ldmatrix.sync.aligned.m8n8.x4.shared.b16 {%0,%1,%2,%3}, [%4];"
                 : "=r"(r[0]), "=r"(r[1]), "=r"(r[2]), "=r"(r[3]) : "r"(a));
}
__device__ __forceinline__ void mma_f16(float* d, const unsigned* a, const unsigned* b)
{
    asm volatile(
        "mma.sync.aligned.m16n8k16.row.col.f32.f16.f16.f32 "
        "{%0,%1,%2,%3}, {%4,%5,%6,%7}, {%8,%9}, {%0,%1,%2,%3};\n"
        : "+f"(d[0]), "+f"(d[1]), "+f"(d[2]), "+f"(d[3])
        : "r"(a[0]), "r"(a[1]), "r"(a[2]), "r"(a[3]), "r"(b[0]), "r"(b[1]));
}

__device__ __forceinline__ float fsig(float x)  { return 1.f / (1.f + __expf(-x)); }
__device__ __forceinline__ float ftanh(float x) { return 1.f - 2.f / (__expf(2.f * x) + 1.f); }

// ---- x -> fp16 fragment-ready layout -----------------------------------------
// frag addr model (A of m16n8k16): value (b,kl) -> lane=((b&7)<<2)|((kl&7)>>1),
// j=((kl>>3)<<1)|(b>>3), half = kl&1 ; chunk = 128 uint32 = 512 B.
extern "C" __global__ void xsplit_kernel(const float* __restrict__ x)
{
    int gid = blockIdx.x * 256 + threadIdx.x;       // 2,097,152 total
    int i0 = (gid & 31) * 4;
    int s  = (gid >> 5) & (SEQ - 1);
    int b  = gid >> 15;
    float4 v = *(const float4*)(x + ((size_t)b * SEQ + s) * IDIM + i0);
    int bl = b & 15, grp = b >> 4;
    int kx = i0 >> 4, kl = i0 & 15;
    int lane = ((bl & 7) << 2) | ((kl & 7) >> 1);
    int j    = ((kl >> 3) << 1) | (bl >> 3);
    uint32_t u0 = (uint32_t)__half_as_ushort(__float2half(v.x)) |
                  ((uint32_t)__half_as_ushort(__float2half(v.y)) << 16);
    uint32_t u1 = (uint32_t)__half_as_ushort(__float2half(v.z)) |
                  ((uint32_t)__half_as_ushort(__float2half(v.w)) << 16);
    size_t base = (((size_t)grp * SEQ + s) * NCH_X + kx) * 128;
    g_xfrag[base + lane * 4 + j]       = u0;
    g_xfrag[base + (lane + 1) * 4 + j] = u1;
}

// ---- persistent LSTM: no barriers in loop, fragment dataflow -----------------
extern "C" __global__ void __launch_bounds__(THREADS, 1)
lstm_kernel(const float* __restrict__ W, const float* __restrict__ U,
            const float* __restrict__ bias,
            const float* __restrict__ fc_w, const float* __restrict__ fc_b,
            float* __restrict__ out)
{
    extern __shared__ char smem[];
    __half* zh = (__half*)(smem + OFF_Z);

    const int tid  = threadIdx.x;
    const int lane = tid & 31;
    const int warp = tid >> 5;
    const int grp  = blockIdx.x >> 5;
    const int gc   = blockIdx.x & 31;
    const int b0   = grp * GB;
    const int h0   = gc * HC;
    const uint32_t smb = (uint32_t)__cvta_generic_to_shared(smem);

    // weights, gate-interleaved local cols: nl -> hid = nl>>2, gate = nl&3
    for (int idx = tid; idx < KTOT * NL; idx += THREADS) {
        int k = idx >> 6, nl = idx & 63;
        int col = (nl & 3) * HDIM + h0 + (nl >> 2);
        float v = (k < HDIM) ? U[(size_t)k * G4 + col]
                             : W[(size_t)(k - HDIM) * G4 + col];
        zh[nl * ZSTR + k] = __float2half(v);
    }
    const int q = (lane >> 1) & 1;
    float bv[2][2];
    #pragma unroll
    for (int t = 0; t < 2; t++) {
        int hid = h0 + warp * 4 + t * 2 + q;
        #pragma unroll
        for (int j = 0; j < 2; j++)
            bv[t][j] = bias[(2 * (lane & 1) + j) * HDIM + hid];
    }
    if (tid == 0) { g_flag[grp][gc][0] = 0; g_done[grp][gc] = 0; }
    __syncthreads();
    if (tid == 0) bar_all(NGRP * NCTA);
    __syncthreads();

    // B fragment base (ldmatrix, validated layout)
    const int brow = warp * 16 + ((lane & 7) | ((lane >> 1) & 8));
    const uint32_t bHiA = smb + OFF_Z + ((brow * ZSTR + (lane & 8)) << 1);
    const uint32_t awb  = smb + OFF_AW + warp * AWSZ + lane * 16;

    const int r = lane >> 2;
    float c0 = 0.f, c1 = 0.f;

    for (int s = 0; s < SEQ; s++) {
        float acc[2][4];
        #pragma unroll
        for (int t = 0; t < 2; t++) {
            acc[t][0] = bv[t][0]; acc[t][1] = bv[t][1];
            acc[t][2] = bv[t][0]; acc[t][3] = bv[t][1];
        }

        // issue x fragment loads (latency hides behind poll)
        uint32_t xv[NCH_X][4];
        {
            const uint4* xb = (const uint4*)(g_xfrag +
                (((size_t)grp * SEQ + s) * NCH_X) * 128 + lane * 4);
            #pragma unroll
            for (int kx = 0; kx < NCH_X; kx++) {
                uint4 t4 = __ldg(xb + kx * 32);
                xv[kx][0] = t4.x; xv[kx][1] = t4.y; xv[kx][2] = t4.z; xv[kx][3] = t4.w;
            }
        }

        if (s > 0) {
            poll_flags(grp, lane, s);
            // stage all 32 h chunks: one warp-wide cp.async per chunk (L1-bypass)
            const char* hsrc = (const char*)g_hfrag +
                ((size_t)((s & 1) * NGRP + grp) * NCTA) * 512 + lane * 16;
            #pragma unroll
            for (int i = 0; i < NCH_H; i++) {
                int kc = (gc + i) & 31;
                cpasync16(awb + kc * 512, hsrc + kc * 512);
            }
        }

        // x-part GEMM (overlaps cp.async flight)
        #pragma unroll
        for (int kx = 0; kx < NCH_X; kx++) {
            unsigned bh[4];
            ldsm4(bh, bHiA + (NCH_H + kx) * 32);
            mma_f16(acc[0], xv[kx], bh);
            mma_f16(acc[1], xv[kx], bh + 2);
        }

        // h-part GEMM
        if (s > 0) {
            cpwait();
            #pragma unroll
            for (int i = 0; i < NCH_H; i++) {
                int kc = (gc + i) & 31;
                unsigned av[4], bh[4];
                lds128(av, awb + kc * 512);
                ldsm4(bh, bHiA + kc * 32);
                mma_f16(acc[0], av, bh);
                mma_f16(acc[1], av, bh + 2);
            }
        }

        // register epilogue -> fragment-layout h store
        char* hdst = (char*)g_hfrag +
            ((size_t)(((s + 1) & 1) * NGRP + grp) * NCTA + gc) * 512;
        #pragma unroll
        for (int t = 0; t < 2; t++) {
            float e0 = __shfl_xor_sync(0xffffffffu, acc[t][0], 1);
            float e1 = __shfl_xor_sync(0xffffffffu, acc[t][1], 1);
            float e2 = __shfl_xor_sync(0xffffffffu, acc[t][2], 1);
            float e3 = __shfl_xor_sync(0xffffffffu, acc[t][3], 1);
            float gi, gf, gg, go;
            int bidx;
            if ((lane & 1) == 0) {
                gi = acc[t][0]; gf = acc[t][1]; gg = e0; go = e1; bidx = r;
            } else {
                gi = e2; gf = e3; gg = acc[t][2]; go = acc[t][3]; bidx = r + 8;
            }
            float i_ = fsig(gi), f_ = fsig(gf), g_ = ftanh(gg), o_ = fsig(go);
            float& cc = t ? c1 : c0;
            cc = f_ * cc + i_ * g_;
            float h = o_ * ftanh(cc);
            int klh = warp * 4 + t * 2 + q;
            int lt  = ((bidx & 7) << 2) | ((klh & 7) >> 1);
            int jt  = ((klh >> 3) << 1) | (bidx >> 3);
            *(__half*)(hdst + lt * 16 + jt * 4 + ((klh & 1) << 1)) = __float2half(h);
            if (s == SEQ - 1) g_hfin[b0 + bidx][h0 + klh] = h;
        }
        // early release: 4th warp publishes
        if (lane == 0) {
            int old = atom_add_acqrel(&g_done[grp][gc], 1);
            if (old == 4 * s + 3)
                asm volatile("st.release.gpu.global.b32 [%0], %1;"
                             :: "l"(&g_flag[grp][gc][0]), "r"(s + 1) : "memory");
        }
    }

    // FC head: one CTA per group, exact fp32 h
    if (gc == 0) {
        poll_flags(grp, lane, SEQ);
        int b = tid >> 3, l8 = tid & 7;
        float a7[7] = {0.f, 0.f, 0.f, 0.f, 0.f, 0.f, 0.f};
        for (int it = 0; it < HDIM / 8; it++) {
            int k = l8 + it * 8;
            float hv;
            asm volatile("ld.relaxed.gpu.global.f32 %0, [%1];"
                         : "=f"(hv) : "l"(&g_hfin[b0 + b][k]));
            #pragma unroll
            for (int o = 0; o < 7; o++) a7[o] += hv * fc_w[k * 7 + o];
        }
        #pragma unroll
        for (int o = 0; o < 7; o++) {
            a7[o] += __shfl_xor_sync(0xffffffffu, a7[o], 4);
            a7[o] += __shfl_xor_sync(0xffffffffu, a7[o], 2);
            a7[o] += __shfl_xor_sync(0xffffffffu, a7[o], 1);
        }
        if (l8 == 0)
            #pragma unroll
            for (int o = 0; o < 7; o++) out[(b0 + b) * 7 + o] = a7[o] + fc_b[o];
    }
}

extern "C" void kernel_launch(void* const* d_in, const int* in_sizes, int n_in,
                              void* d_out, int out_size)
{
    (void)in_sizes; (void)n_in; (void)out_size;
    const float* x    = (const float*)d_in[0];
    const float* W    = (const float*)d_in[1];
    const float* U    = (const float*)d_in[2];
    const float* bias = (const float*)d_in[3];
    const float* fc_w = (const float*)d_in[4];
    const float* fc_b = (const float*)d_in[5];

    cudaFuncSetAttribute(lstm_kernel,
                         cudaFuncAttributeMaxDynamicSharedMemorySize, SMEM_SZ);
    xsplit_kernel<<<BATCH * SEQ * IDIM / 1024, 256>>>(x);
    lstm_kernel<<<NGRP * NCTA, THREADS, SMEM_SZ>>>(W, U, bias, fc_w, fc_b, (float*)d_out);
}

// round 6
// speedup vs baseline: 1.4485x; 1.4485x over previous
#include <cuda_runtime.h>
#include <cuda_fp16.h>
#include <cstdint>

#define BATCH   64
#define SEQ     1024
#define IDIM    128
#define HDIM    512
#define G4      2048
#define KTOT    640
#define NGRP    4
#define GB      16
#define NCTA    32
#define HC      16
#define NL      64
#define THREADS 128
#define NCH_H   32
#define NCH_X   8

#define ZSTR    648
#define OFF_Z   0
#define OFF_A   (NL * ZSTR * 2)          // 82944 : shared 16KB h staging
#define SMEM_SZ (OFF_A + NCH_H * 512)    // 99328 B

// ---- global scratch (static) -------------------------------------------------
__device__ uint32_t g_xfrag[(size_t)NGRP * SEQ * NCH_X * 128];  // x in frag layout
__device__ uint32_t g_hfrag[2 * NGRP * NCTA * 128];             // ping-pong h chunks
__device__ float    g_hfin[BATCH][HDIM];                        // exact final h
__device__ int      g_step[NGRP][32];                           // 128B-padded counter
__device__ int      g_cnt, g_gen;

// ---- prologue-only global barrier (replay-safe) ------------------------------
__device__ __forceinline__ void bar_all(int n)
{
    int my;
    asm volatile("ld.acquire.gpu.global.b32 %0, [%1];" : "=r"(my) : "l"(&g_gen));
    __threadfence();
    if (atomicAdd(&g_cnt, 1) == n - 1) {
        atomicExch(&g_cnt, 0);
        __threadfence();
        atomicAdd(&g_gen, 1);
    } else {
        int v;
        do { asm volatile("ld.acquire.gpu.global.b32 %0, [%1];" : "=r"(v) : "l"(&g_gen)); }
        while (v == my);
    }
}

// poll single group counter until >= need (all lanes, one coalesced line)
__device__ __forceinline__ void poll_cnt(int grp, int need)
{
    const int* p = &g_step[grp][0];
    int v;
    do { asm volatile("ld.acquire.gpu.global.b32 %0, [%1];" : "=r"(v) : "l"(p)); }
    while (v < need);
}

__device__ __forceinline__ void release_inc(int grp)
{
    asm volatile("red.add.release.gpu.global.s32 [%0], 1;"
                 :: "l"(&g_step[grp][0]) : "memory");
}

__device__ __forceinline__ void cpasync16(uint32_t dst, const void* src)
{
    asm volatile("cp.async.cg.shared.global [%0], [%1], 16;" :: "r"(dst), "l"(src));
}
__device__ __forceinline__ void cpwait()
{
    asm volatile("cp.async.wait_all;" ::: "memory");
}

__device__ __forceinline__ void lds128(unsigned r[4], uint32_t a)
{
    asm volatile("ld.shared.v4.b32 {%0,%1,%2,%3}, [%4];"
                 : "=r"(r[0]), "=r"(r[1]), "=r"(r[2]), "=r"(r[3]) : "r"(a));
}
__device__ __forceinline__ void ldsm4(unsigned r[4], uint32_t a)
{
    asm volatile("ldmatrix.sync.aligned.m8n8.x4.shared.b16 {%0,%1,%2,%3}, [%4];"
                 : "=r"(r[0]), "=r"(r[1]), "=r"(r[2]), "=r"(r[3]) : "r"(a));
}
__device__ __forceinline__ void mma_f16(float* d, const unsigned* a, const unsigned* b)
{
    asm volatile(
        "mma.sync.aligned.m16n8k16.row.col.f32.f16.f16.f32 "
        "{%0,%1,%2,%3}, {%4,%5,%6,%7}, {%8,%9}, {%0,%1,%2,%3};\n"
        : "+f"(d[0]), "+f"(d[1]), "+f"(d[2]), "+f"(d[3])
        : "r"(a[0]), "r"(a[1]), "r"(a[2]), "r"(a[3]), "r"(b[0]), "r"(b[1]));
}

__device__ __forceinline__ float fsig(float x)  { return 1.f / (1.f + __expf(-x)); }
__device__ __forceinline__ float ftanh(float x) { return 1.f - 2.f / (__expf(2.f * x) + 1.f); }

// ---- x -> fp16 fragment-ready layout (validated R5) --------------------------
extern "C" __global__ void xsplit_kernel(const float* __restrict__ x)
{
    int gid = blockIdx.x * 256 + threadIdx.x;
    int i0 = (gid & 31) * 4;
    int s  = (gid >> 5) & (SEQ - 1);
    int b  = gid >> 15;
    float4 v = *(const float4*)(x + ((size_t)b * SEQ + s) * IDIM + i0);
    int bl = b & 15, grp = b >> 4;
    int kx = i0 >> 4, kl = i0 & 15;
    int lane = ((bl & 7) << 2) | ((kl & 7) >> 1);
    int j    = ((kl >> 3) << 1) | (bl >> 3);
    uint32_t u0 = (uint32_t)__half_as_ushort(__float2half(v.x)) |
                  ((uint32_t)__half_as_ushort(__float2half(v.y)) << 16);
    uint32_t u1 = (uint32_t)__half_as_ushort(__float2half(v.z)) |
                  ((uint32_t)__half_as_ushort(__float2half(v.w)) << 16);
    size_t base = (((size_t)grp * SEQ + s) * NCH_X + kx) * 128;
    g_xfrag[base + lane * 4 + j]       = u0;
    g_xfrag[base + (lane + 1) * 4 + j] = u1;
}

// ---- persistent LSTM ---------------------------------------------------------
extern "C" __global__ void __launch_bounds__(THREADS, 1)
lstm_kernel(const float* __restrict__ W, const float* __restrict__ U,
            const float* __restrict__ bias,
            const float* __restrict__ fc_w, const float* __restrict__ fc_b,
            float* __restrict__ out)
{
    extern __shared__ char smem[];
    __half* zh = (__half*)(smem + OFF_Z);

    const int tid  = threadIdx.x;
    const int lane = tid & 31;
    const int warp = tid >> 5;
    const int grp  = blockIdx.x >> 5;
    const int gc   = blockIdx.x & 31;
    const int b0   = grp * GB;
    const int h0   = gc * HC;
    const uint32_t smb = (uint32_t)__cvta_generic_to_shared(smem);

    // weights, gate-interleaved local cols: nl -> hid = nl>>2, gate = nl&3
    for (int idx = tid; idx < KTOT * NL; idx += THREADS) {
        int k = idx >> 6, nl = idx & 63;
        int col = (nl & 3) * HDIM + h0 + (nl >> 2);
        float v = (k < HDIM) ? U[(size_t)k * G4 + col]
                             : W[(size_t)(k - HDIM) * G4 + col];
        zh[nl * ZSTR + k] = __float2half(v);
    }
    const int q = (lane >> 1) & 1;
    float bv[2][2];
    #pragma unroll
    for (int t = 0; t < 2; t++) {
        int hid = h0 + warp * 4 + t * 2 + q;
        #pragma unroll
        for (int j = 0; j < 2; j++)
            bv[t][j] = bias[(2 * (lane & 1) + j) * HDIM + hid];
    }
    if (tid == 0 && gc == 0) g_step[grp][0] = 0;   // replay-safe reset
    __syncthreads();
    if (tid == 0) bar_all(NGRP * NCTA);
    __syncthreads();

    // B fragment base (ldmatrix, validated layout)
    const int brow = warp * 16 + ((lane & 7) | ((lane >> 1) & 8));
    const uint32_t bHiA = smb + OFF_Z + ((brow * ZSTR + (lane & 8)) << 1);
    const uint32_t aStg = smb + OFF_A + lane * 16;

    const int r = lane >> 2;
    float c0 = 0.f, c1 = 0.f;

    for (int s = 0; s < SEQ; s++) {
        float acc[2][4];
        #pragma unroll
        for (int t = 0; t < 2; t++) {
            acc[t][0] = bv[t][0]; acc[t][1] = bv[t][1];
            acc[t][2] = bv[t][0]; acc[t][3] = bv[t][1];
        }

        // x fragment loads (issued before the poll; latency hidden)
        uint32_t xv[NCH_X][4];
        {
            const uint4* xb = (const uint4*)(g_xfrag +
                (((size_t)grp * SEQ + s) * NCH_X) * 128 + lane * 4);
            #pragma unroll
            for (int kx = 0; kx < NCH_X; kx++) {
                uint4 t4 = __ldg(xb + kx * 32);
                xv[kx][0] = t4.x; xv[kx][1] = t4.y; xv[kx][2] = t4.z; xv[kx][3] = t4.w;
            }
        }

        if (s > 0) {
            poll_cnt(grp, 128 * s);
            __syncthreads();  // everyone past previous step's smem reads
            // stage 8 chunks per warp into SHARED buffer (16KB/CTA total)
            const char* hsrc = (const char*)g_hfrag +
                ((size_t)((s & 1) * NGRP + grp) * NCTA) * 512 + lane * 16;
            #pragma unroll
            for (int i = 0; i < 8; i++) {
                int kc = warp * 8 + i;
                cpasync16(aStg + kc * 512, hsrc + kc * 512);
            }
        }

        // x-part GEMM (overlaps cp.async flight)
        #pragma unroll
        for (int kx = 0; kx < NCH_X; kx++) {
            unsigned bh[4];
            ldsm4(bh, bHiA + (NCH_H + kx) * 32);
            mma_f16(acc[0], xv[kx], bh);
            mma_f16(acc[1], xv[kx], bh + 2);
        }

        // h-part GEMM
        if (s > 0) {
            cpwait();
            __syncthreads();  // all 32 chunks staged
            #pragma unroll 8
            for (int kc = 0; kc < NCH_H; kc++) {
                unsigned av[4], bh[4];
                lds128(av, aStg + kc * 512);
                ldsm4(bh, bHiA + kc * 32);
                mma_f16(acc[0], av, bh);
                mma_f16(acc[1], av, bh + 2);
            }
        }

        // register epilogue -> fragment-layout h store
        char* hdst = (char*)g_hfrag +
            ((size_t)(((s + 1) & 1) * NGRP + grp) * NCTA + gc) * 512;
        #pragma unroll
        for (int t = 0; t < 2; t++) {
            float e0 = __shfl_xor_sync(0xffffffffu, acc[t][0], 1);
            float e1 = __shfl_xor_sync(0xffffffffu, acc[t][1], 1);
            float e2 = __shfl_xor_sync(0xffffffffu, acc[t][2], 1);
            float e3 = __shfl_xor_sync(0xffffffffu, acc[t][3], 1);
            float gi, gf, gg, go;
            int bidx;
            if ((lane & 1) == 0) {
                gi = acc[t][0]; gf = acc[t][1]; gg = e0; go = e1; bidx = r;
            } else {
                gi = e2; gf = e3; gg = acc[t][2]; go = acc[t][3]; bidx = r + 8;
            }
            float i_ = fsig(gi), f_ = fsig(gf), g_ = ftanh(gg), o_ = fsig(go);
            float& cc = t ? c1 : c0;
            cc = f_ * cc + i_ * g_;
            float h = o_ * ftanh(cc);
            int klh = warp * 4 + t * 2 + q;
            int lt  = ((bidx & 7) << 2) | ((klh & 7) >> 1);
            int jt  = ((klh >> 3) << 1) | (bidx >> 3);
            *(__half*)(hdst + lt * 16 + jt * 4 + ((klh & 1) << 1)) = __float2half(h);
            if (s == SEQ - 1) g_hfin[b0 + bidx][h0 + klh] = h;
        }
        // one release-increment per warp; consumer target = 128 * step
        if (lane == 0) release_inc(grp);
    }

    // FC head: one CTA per group, exact fp32 h
    if (gc == 0) {
        poll_cnt(grp, 128 * SEQ);
        int b = tid >> 3, l8 = tid & 7;
        float a7[7] = {0.f, 0.f, 0.f, 0.f, 0.f, 0.f, 0.f};
        for (int it = 0; it < HDIM / 8; it++) {
            int k = l8 + it * 8;
            float hv;
            asm volatile("ld.relaxed.gpu.global.f32 %0, [%1];"
                         : "=f"(hv) : "l"(&g_hfin[b0 + b][k]));
            #pragma unroll
            for (int o = 0; o < 7; o++) a7[o] += hv * fc_w[k * 7 + o];
        }
        #pragma unroll
        for (int o = 0; o < 7; o++) {
            a7[o] += __shfl_xor_sync(0xffffffffu, a7[o], 4);
            a7[o] += __shfl_xor_sync(0xffffffffu, a7[o], 2);
            a7[o] += __shfl_xor_sync(0xffffffffu, a7[o], 1);
        }
        if (l8 == 0)
            #pragma unroll
            for (int o = 0; o < 7; o++) out[(b0 + b) * 7 + o] = a7[o] + fc_b[o];
    }
}

extern "C" void kernel_launch(void* const* d_in, const int* in_sizes, int n_in,
                              void* d_out, int out_size)
{
    (void)in_sizes; (void)n_in; (void)out_size;
    const float* x    = (const float*)d_in[0];
    const float* W    = (const float*)d_in[1];
    const float* U    = (const float*)d_in[2];
    const float* bias = (const float*)d_in[3];
    const float* fc_w = (const float*)d_in[4];
    const float* fc_b = (const float*)d_in[5];

    cudaFuncSetAttribute(lstm_kernel,
                         cudaFuncAttributeMaxDynamicSharedMemorySize, SMEM_SZ);
    xsplit_kernel<<<BATCH * SEQ * IDIM / 1024, 256>>>(x);
    lstm_kernel<<<NGRP * NCTA, THREADS, SMEM_SZ>>>(W, U, bias, fc_w, fc_b, (float*)d_out);
}

// round 7
// speedup vs baseline: 1.6296x; 1.1250x over previous
#include <cuda_runtime.h>
#include <cuda_fp16.h>
#include <cstdint>

#define BATCH   64
#define SEQ     1024
#define IDIM    128
#define HDIM    512
#define G4      2048
#define KTOT    640
#define NGRP    4
#define GB      16
#define NCTA    32
#define HC      16
#define NL      64
#define THREADS 128
#define NCH_H   32
#define NCH_X   8
#define NCH     40

#define ZSTR    648
#define OFF_Z   0
#define OFF_A   (NL * ZSTR * 2)          // 82944 : shared 16KB h staging
#define SMEM_SZ (OFF_A + NCH_H * 512)    // 99328 B

// ---- global scratch (static) -------------------------------------------------
__device__ uint32_t g_xfrag[(size_t)NGRP * SEQ * NCH_X * 128];  // x in frag layout
__device__ uint32_t g_hfrag[2 * NGRP * NCTA * 128];             // ping-pong h chunks
__device__ float    g_hfin[BATCH][HDIM];                        // exact final h
__device__ int      g_step[NGRP][32];                           // 128B-padded counter
__device__ int      g_cnt, g_gen;

// ---- prologue-only global barrier (replay-safe) ------------------------------
__device__ __forceinline__ void bar_all(int n)
{
    int my;
    asm volatile("ld.acquire.gpu.global.b32 %0, [%1];" : "=r"(my) : "l"(&g_gen));
    __threadfence();
    if (atomicAdd(&g_cnt, 1) == n - 1) {
        atomicExch(&g_cnt, 0);
        __threadfence();
        atomicAdd(&g_gen, 1);
    } else {
        int v;
        do { asm volatile("ld.acquire.gpu.global.b32 %0, [%1];" : "=r"(v) : "l"(&g_gen)); }
        while (v == my);
    }
}

__device__ __forceinline__ void poll_cnt(int grp, int need)
{
    const int* p = &g_step[grp][0];
    int v;
    do { asm volatile("ld.acquire.gpu.global.b32 %0, [%1];" : "=r"(v) : "l"(p)); }
    while (v < need);
}

__device__ __forceinline__ void release_inc(int grp)
{
    asm volatile("red.add.release.gpu.global.s32 [%0], 1;"
                 :: "l"(&g_step[grp][0]) : "memory");
}

__device__ __forceinline__ void cpasync16(uint32_t dst, const void* src)
{
    asm volatile("cp.async.cg.shared.global [%0], [%1], 16;" :: "r"(dst), "l"(src));
}
__device__ __forceinline__ void cpwait()
{
    asm volatile("cp.async.wait_all;" ::: "memory");
}

__device__ __forceinline__ void lds128(unsigned r[4], uint32_t a)
{
    asm volatile("ld.shared.v4.b32 {%0,%1,%2,%3}, [%4];"
                 : "=r"(r[0]), "=r"(r[1]), "=r"(r[2]), "=r"(r[3]) : "r"(a));
}
__device__ __forceinline__ void ldsm4(unsigned r[4], uint32_t a)
{
    asm volatile("ldmatrix.sync.aligned.m8n8.x4.shared.b16 {%0,%1,%2,%3}, [%4];"
                 : "=r"(r[0]), "=r"(r[1]), "=r"(r[2]), "=r"(r[3]) : "r"(a));
}
__device__ __forceinline__ void mma_f16(float* d, const unsigned* a, const unsigned* b)
{
    asm volatile(
        "mma.sync.aligned.m16n8k16.row.col.f32.f16.f16.f32 "
        "{%0,%1,%2,%3}, {%4,%5,%6,%7}, {%8,%9}, {%0,%1,%2,%3};\n"
        : "+f"(d[0]), "+f"(d[1]), "+f"(d[2]), "+f"(d[3])
        : "r"(a[0]), "r"(a[1]), "r"(a[2]), "r"(a[3]), "r"(b[0]), "r"(b[1]));
}

__device__ __forceinline__ float fsig(float x)  { return 1.f / (1.f + __expf(-x)); }
__device__ __forceinline__ float ftanh(float x) { return 1.f - 2.f / (__expf(2.f * x) + 1.f); }

// ---- x -> fp16 fragment-ready layout (validated) -----------------------------
extern "C" __global__ void xsplit_kernel(const float* __restrict__ x)
{
    int gid = blockIdx.x * 256 + threadIdx.x;
    int i0 = (gid & 31) * 4;
    int s  = (gid >> 5) & (SEQ - 1);
    int b  = gid >> 15;
    float4 v = *(const float4*)(x + ((size_t)b * SEQ + s) * IDIM + i0);
    int bl = b & 15, grp = b >> 4;
    int kx = i0 >> 4, kl = i0 & 15;
    int lane = ((bl & 7) << 2) | ((kl & 7) >> 1);
    int j    = ((kl >> 3) << 1) | (bl >> 3);
    uint32_t u0 = (uint32_t)__half_as_ushort(__float2half(v.x)) |
                  ((uint32_t)__half_as_ushort(__float2half(v.y)) << 16);
    uint32_t u1 = (uint32_t)__half_as_ushort(__float2half(v.z)) |
                  ((uint32_t)__half_as_ushort(__float2half(v.w)) << 16);
    size_t base = (((size_t)grp * SEQ + s) * NCH_X + kx) * 128;
    g_xfrag[base + lane * 4 + j]       = u0;
    g_xfrag[base + (lane + 1) * 4 + j] = u1;
}

// ---- persistent LSTM: B weights resident in REGISTERS ------------------------
extern "C" __global__ void __launch_bounds__(THREADS, 1)
lstm_kernel(const float* __restrict__ W, const float* __restrict__ U,
            const float* __restrict__ bias,
            const float* __restrict__ fc_w, const float* __restrict__ fc_b,
            float* __restrict__ out)
{
    extern __shared__ char smem[];
    __half* zh = (__half*)(smem + OFF_Z);

    const int tid  = threadIdx.x;
    const int lane = tid & 31;
    const int warp = tid >> 5;
    const int grp  = blockIdx.x >> 5;
    const int gc   = blockIdx.x & 31;
    const int b0   = grp * GB;
    const int h0   = gc * HC;
    const uint32_t smb = (uint32_t)__cvta_generic_to_shared(smem);

    // weights into smem, gate-interleaved local cols: nl -> hid=nl>>2, gate=nl&3
    for (int idx = tid; idx < KTOT * NL; idx += THREADS) {
        int k = idx >> 6, nl = idx & 63;
        int col = (nl & 3) * HDIM + h0 + (nl >> 2);
        float v = (k < HDIM) ? U[(size_t)k * G4 + col]
                             : W[(size_t)(k - HDIM) * G4 + col];
        zh[nl * ZSTR + k] = __float2half(v);
    }
    const int q = (lane >> 1) & 1;
    float bv[2][2];
    #pragma unroll
    for (int t = 0; t < 2; t++) {
        int hid = h0 + warp * 4 + t * 2 + q;
        #pragma unroll
        for (int j = 0; j < 2; j++)
            bv[t][j] = bias[(2 * (lane & 1) + j) * HDIM + hid];
    }
    if (tid == 0 && gc == 0) g_step[grp][0] = 0;   // replay-safe reset
    __syncthreads();

    // hoist ALL B fragments into registers (loop-invariant across 1024 steps)
    const int brow = warp * 16 + ((lane & 7) | ((lane >> 1) & 8));
    const uint32_t bHiA = smb + OFF_Z + ((brow * ZSTR + (lane & 8)) << 1);
    unsigned bfr[NCH][4];
    #pragma unroll
    for (int kc = 0; kc < NCH; kc++)
        ldsm4(bfr[kc], bHiA + kc * 32);

    if (tid == 0) bar_all(NGRP * NCTA);
    __syncthreads();

    const uint32_t aStg = smb + OFF_A + lane * 16;
    const int r = lane >> 2;
    float c0 = 0.f, c1 = 0.f;

    for (int s = 0; s < SEQ; s++) {
        float acc[2][4];
        #pragma unroll
        for (int t = 0; t < 2; t++) {
            acc[t][0] = bv[t][0]; acc[t][1] = bv[t][1];
            acc[t][2] = bv[t][0]; acc[t][3] = bv[t][1];
        }

        // x fragment loads (issued before the poll; latency hidden)
        uint32_t xv[NCH_X][4];
        {
            const uint4* xb = (const uint4*)(g_xfrag +
                (((size_t)grp * SEQ + s) * NCH_X) * 128 + lane * 4);
            #pragma unroll
            for (int kx = 0; kx < NCH_X; kx++) {
                uint4 t4 = __ldg(xb + kx * 32);
                xv[kx][0] = t4.x; xv[kx][1] = t4.y; xv[kx][2] = t4.z; xv[kx][3] = t4.w;
            }
        }

        if (s > 0) {
            poll_cnt(grp, 128 * s);
            __syncthreads();  // everyone past previous step's smem reads
            const char* hsrc = (const char*)g_hfrag +
                ((size_t)((s & 1) * NGRP + grp) * NCTA) * 512 + lane * 16;
            #pragma unroll
            for (int i = 0; i < 8; i++) {
                int kc = warp * 8 + i;
                cpasync16(aStg + kc * 512, hsrc + kc * 512);
            }
        }

        // x-part GEMM (regs only; overlaps cp.async flight)
        #pragma unroll
        for (int kx = 0; kx < NCH_X; kx++) {
            mma_f16(acc[0], xv[kx], bfr[NCH_H + kx]);
            mma_f16(acc[1], xv[kx], bfr[NCH_H + kx] + 2);
        }

        // h-part GEMM: LDS.128 + 2 MMA per chunk, B from registers
        if (s > 0) {
            cpwait();
            __syncthreads();
            #pragma unroll
            for (int kc = 0; kc < NCH_H; kc++) {
                unsigned av[4];
                lds128(av, aStg + kc * 512);
                mma_f16(acc[0], av, bfr[kc]);
                mma_f16(acc[1], av, bfr[kc] + 2);
            }
        }

        // register epilogue -> fragment-layout h store
        char* hdst = (char*)g_hfrag +
            ((size_t)(((s + 1) & 1) * NGRP + grp) * NCTA + gc) * 512;
        #pragma unroll
        for (int t = 0; t < 2; t++) {
            float e0 = __shfl_xor_sync(0xffffffffu, acc[t][0], 1);
            float e1 = __shfl_xor_sync(0xffffffffu, acc[t][1], 1);
            float e2 = __shfl_xor_sync(0xffffffffu, acc[t][2], 1);
            float e3 = __shfl_xor_sync(0xffffffffu, acc[t][3], 1);
            float gi, gf, gg, go;
            int bidx;
            if ((lane & 1) == 0) {
                gi = acc[t][0]; gf = acc[t][1]; gg = e0; go = e1; bidx = r;
            } else {
                gi = e2; gf = e3; gg = acc[t][2]; go = acc[t][3]; bidx = r + 8;
            }
            float i_ = fsig(gi), f_ = fsig(gf), g_ = ftanh(gg), o_ = fsig(go);
            float& cc = t ? c1 : c0;
            cc = f_ * cc + i_ * g_;
            float h = o_ * ftanh(cc);
            int klh = warp * 4 + t * 2 + q;
            int lt  = ((bidx & 7) << 2) | ((klh & 7) >> 1);
            int jt  = ((klh >> 3) << 1) | (bidx >> 3);
            *(__half*)(hdst + lt * 16 + jt * 4 + ((klh & 1) << 1)) = __float2half(h);
            if (s == SEQ - 1) g_hfin[b0 + bidx][h0 + klh] = h;
        }
        if (lane == 0) release_inc(grp);
    }

    // FC head: one CTA per group, exact fp32 h
    if (gc == 0) {
        poll_cnt(grp, 128 * SEQ);
        int b = tid >> 3, l8 = tid & 7;
        float a7[7] = {0.f, 0.f, 0.f, 0.f, 0.f, 0.f, 0.f};
        for (int it = 0; it < HDIM / 8; it++) {
            int k = l8 + it * 8;
            float hv;
            asm volatile("ld.relaxed.gpu.global.f32 %0, [%1];"
                         : "=f"(hv) : "l"(&g_hfin[b0 + b][k]));
            #pragma unroll
            for (int o = 0; o < 7; o++) a7[o] += hv * fc_w[k * 7 + o];
        }
        #pragma unroll
        for (int o = 0; o < 7; o++) {
            a7[o] += __shfl_xor_sync(0xffffffffu, a7[o], 4);
            a7[o] += __shfl_xor_sync(0xffffffffu, a7[o], 2);
            a7[o] += __shfl_xor_sync(0xffffffffu, a7[o], 1);
        }
        if (l8 == 0)
            #pragma unroll
            for (int o = 0; o < 7; o++) out[(b0 + b) * 7 + o] = a7[o] + fc_b[o];
    }
}

extern "C" void kernel_launch(void* const* d_in, const int* in_sizes, int n_in,
                              void* d_out, int out_size)
{
    (void)in_sizes; (void)n_in; (void)out_size;
    const float* x    = (const float*)d_in[0];
    const float* W    = (const float*)d_in[1];
    const float* U    = (const float*)d_in[2];
    const float* bias = (const float*)d_in[3];
    const float* fc_w = (const float*)d_in[4];
    const float* fc_b = (const float*)d_in[5];

    cudaFuncSetAttribute(lstm_kernel,
                         cudaFuncAttributeMaxDynamicSharedMemorySize, SMEM_SZ);
    xsplit_kernel<<<BATCH * SEQ * IDIM / 1024, 256>>>(x);
    lstm_kernel<<<NGRP * NCTA, THREADS, SMEM_SZ>>>(W, U, bias, fc_w, fc_b, (float*)d_out);
}

// round 9
// speedup vs baseline: 1.6780x; 1.0297x over previous
#include <cuda_runtime.h>
#include <cuda_fp16.h>
#include <cstdint>

#define BATCH   64
#define SEQ     1024
#define IDIM    128
#define HDIM    512
#define G4      2048
#define KTOT    640
#define NGRP    4
#define GB      16
#define NCTA    32
#define HC      16
#define NL      64
#define THREADS 128
#define NCH_H   32
#define NCH_X   8
#define NCH     40

#define ZSTR     648
#define OFF_Z    0
#define OFF_A0   (NL * ZSTR * 2)            // 82944 : staging buf 0 (16KB)
#define OFF_A1   (OFF_A0 + NCH_H * 512)     // 99328 : staging buf 1 (16KB)
#define OFF_MBAR (OFF_A1 + NCH_H * 512)     // 115712
#define SMEM_SZ  (OFF_MBAR + 16)            // 115728 B

// ---- global scratch (static) -------------------------------------------------
__device__ uint32_t g_xfrag[(size_t)NGRP * SEQ * NCH_X * 128];  // x in frag layout
__device__ uint32_t g_hfrag[2 * NGRP * NCTA * 128];             // ping-pong h chunks
__device__ float    g_hfin[BATCH][HDIM];                        // exact final h
__device__ int      g_step[NGRP][32];                           // 128B-padded counter
__device__ int      g_cnt, g_gen;

// ---- prologue-only global barrier (replay-safe) ------------------------------
__device__ __forceinline__ void bar_all(int n)
{
    int my;
    asm volatile("ld.acquire.gpu.global.b32 %0, [%1];" : "=r"(my) : "l"(&g_gen));
    __threadfence();
    if (atomicAdd(&g_cnt, 1) == n - 1) {
        atomicExch(&g_cnt, 0);
        __threadfence();
        atomicAdd(&g_gen, 1);
    } else {
        int v;
        do { asm volatile("ld.acquire.gpu.global.b32 %0, [%1];" : "=r"(v) : "l"(&g_gen)); }
        while (v == my);
    }
}

__device__ __forceinline__ void poll_cnt(int grp, int need)
{
    const int* p = &g_step[grp][0];
    int v;
    do { asm volatile("ld.acquire.gpu.global.b32 %0, [%1];" : "=r"(v) : "l"(p)); }
    while (v < need);
}

__device__ __forceinline__ void release_inc(int grp)
{
    asm volatile("red.add.release.gpu.global.s32 [%0], 1;"
                 :: "l"(&g_step[grp][0]) : "memory");
}

__device__ __forceinline__ void cpasync16(uint32_t dst, const void* src)
{
    asm volatile("cp.async.cg.shared.global [%0], [%1], 16;" :: "r"(dst), "l"(src));
}
// .noinc is load-bearing: default variant pre-increments the pending count
// (net zero per arrive) and the phase can never complete -> deadlock (R8).
__device__ __forceinline__ void cp_mbar_arrive(uint32_t mbar)
{
    asm volatile("cp.async.mbarrier.arrive.noinc.shared::cta.b64 [%0];"
                 :: "r"(mbar) : "memory");
}
__device__ __forceinline__ void mbar_init(uint32_t mbar, int cnt)
{
    asm volatile("mbarrier.init.shared.b64 [%0], %1;" :: "r"(mbar), "r"(cnt) : "memory");
}
__device__ __forceinline__ void mbar_wait(uint32_t mbar, uint32_t parity)
{
    asm volatile(
        "{\n\t"
        ".reg .pred P;\n\t"
        "WAIT_%=:\n\t"
        "mbarrier.try_wait.parity.acquire.cta.shared::cta.b64 P, [%0], %1, 0x989680;\n\t"
        "@P bra.uni DONE_%=;\n\t"
        "bra.uni WAIT_%=;\n\t"
        "DONE_%=:\n\t"
        "}"
        :: "r"(mbar), "r"(parity) : "memory");
}

__device__ __forceinline__ void lds128(unsigned r[4], uint32_t a)
{
    asm volatile("ld.shared.v4.b32 {%0,%1,%2,%3}, [%4];"
                 : "=r"(r[0]), "=r"(r[1]), "=r"(r[2]), "=r"(r[3]) : "r"(a));
}
__device__ __forceinline__ void ldsm4(unsigned r[4], uint32_t a)
{
    asm volatile("ldmatrix.sync.aligned.m8n8.x4.shared.b16 {%0,%1,%2,%3}, [%4];"
                 : "=r"(r[0]), "=r"(r[1]), "=r"(r[2]), "=r"(r[3]) : "r"(a));
}
__device__ __forceinline__ void mma_f16(float* d, const unsigned* a, const unsigned* b)
{
    asm volatile(
        "mma.sync.aligned.m16n8k16.row.col.f32.f16.f16.f32 "
        "{%0,%1,%2,%3}, {%4,%5,%6,%7}, {%8,%9}, {%0,%1,%2,%3};\n"
        : "+f"(d[0]), "+f"(d[1]), "+f"(d[2]), "+f"(d[3])
        : "r"(a[0]), "r"(a[1]), "r"(a[2]), "r"(a[3]), "r"(b[0]), "r"(b[1]));
}

__device__ __forceinline__ float fsig(float x)  { return 1.f / (1.f + __expf(-x)); }
__device__ __forceinline__ float ftanh(float x) { return 1.f - 2.f / (__expf(2.f * x) + 1.f); }

// ---- x -> fp16 fragment-ready layout (validated) -----------------------------
extern "C" __global__ void xsplit_kernel(const float* __restrict__ x)
{
    int gid = blockIdx.x * 256 + threadIdx.x;
    int i0 = (gid & 31) * 4;
    int s  = (gid >> 5) & (SEQ - 1);
    int b  = gid >> 15;
    float4 v = *(const float4*)(x + ((size_t)b * SEQ + s) * IDIM + i0);
    int bl = b & 15, grp = b >> 4;
    int kx = i0 >> 4, kl = i0 & 15;
    int lane = ((bl & 7) << 2) | ((kl & 7) >> 1);
    int j    = ((kl >> 3) << 1) | (bl >> 3);
    uint32_t u0 = (uint32_t)__half_as_ushort(__float2half(v.x)) |
                  ((uint32_t)__half_as_ushort(__float2half(v.y)) << 16);
    uint32_t u1 = (uint32_t)__half_as_ushort(__float2half(v.z)) |
                  ((uint32_t)__half_as_ushort(__float2half(v.w)) << 16);
    size_t base = (((size_t)grp * SEQ + s) * NCH_X + kx) * 128;
    g_xfrag[base + lane * 4 + j]       = u0;
    g_xfrag[base + (lane + 1) * 4 + j] = u1;
}

// ---- persistent LSTM: reg-resident B, 4 acc chains, mbarrier staging ---------
extern "C" __global__ void __launch_bounds__(THREADS, 1)
lstm_kernel(const float* __restrict__ W, const float* __restrict__ U,
            const float* __restrict__ bias,
            const float* __restrict__ fc_w, const float* __restrict__ fc_b,
            float* __restrict__ out)
{
    extern __shared__ char smem[];
    __half* zh = (__half*)(smem + OFF_Z);

    const int tid  = threadIdx.x;
    const int lane = tid & 31;
    const int warp = tid >> 5;
    const int grp  = blockIdx.x >> 5;
    const int gc   = blockIdx.x & 31;
    const int b0   = grp * GB;
    const int h0   = gc * HC;
    const uint32_t smb  = (uint32_t)__cvta_generic_to_shared(smem);
    const uint32_t mbar = smb + OFF_MBAR;

    // weights into smem, gate-interleaved local cols: nl -> hid=nl>>2, gate=nl&3
    for (int idx = tid; idx < KTOT * NL; idx += THREADS) {
        int k = idx >> 6, nl = idx & 63;
        int col = (nl & 3) * HDIM + h0 + (nl >> 2);
        float v = (k < HDIM) ? U[(size_t)k * G4 + col]
                             : W[(size_t)(k - HDIM) * G4 + col];
        zh[nl * ZSTR + k] = __float2half(v);
    }
    const int q = (lane >> 1) & 1;
    float bv[2][2];
    #pragma unroll
    for (int t = 0; t < 2; t++) {
        int hid = h0 + warp * 4 + t * 2 + q;
        #pragma unroll
        for (int j = 0; j < 2; j++)
            bv[t][j] = bias[(2 * (lane & 1) + j) * HDIM + hid];
    }
    if (tid == 0) {
        if (gc == 0) g_step[grp][0] = 0;   // replay-safe reset
        mbar_init(mbar, THREADS);
    }
    __syncthreads();

    // hoist ALL B fragments into registers (loop-invariant across 1024 steps)
    const int brow = warp * 16 + ((lane & 7) | ((lane >> 1) & 8));
    const uint32_t bHiA = smb + OFF_Z + ((brow * ZSTR + (lane & 8)) << 1);
    unsigned bfr[NCH][4];
    #pragma unroll
    for (int kc = 0; kc < NCH; kc++)
        ldsm4(bfr[kc], bHiA + kc * 32);

    if (tid == 0) bar_all(NGRP * NCTA);
    __syncthreads();

    const int r = lane >> 2;
    const int jt_c = (warp >> 1) << 1;
    const int lt_c = (warp & 1) << 1;
    float c0 = 0.f, c1 = 0.f;

    for (int s = 0; s < SEQ; s++) {
        // 4 accumulator chains: [t][even/odd]
        float accA[2][4], accB[2][4];
        #pragma unroll
        for (int t = 0; t < 2; t++) {
            accA[t][0] = bv[t][0]; accA[t][1] = bv[t][1];
            accA[t][2] = bv[t][0]; accA[t][3] = bv[t][1];
            accB[t][0] = 0.f; accB[t][1] = 0.f;
            accB[t][2] = 0.f; accB[t][3] = 0.f;
        }

        // x fragment loads (issued before the poll; latency hidden)
        uint32_t xv[NCH_X][4];
        {
            const uint4* xb = (const uint4*)(g_xfrag +
                (((size_t)grp * SEQ + s) * NCH_X) * 128 + lane * 4);
            #pragma unroll
            for (int kx = 0; kx < NCH_X; kx++) {
                uint4 t4 = __ldg(xb + kx * 32);
                xv[kx][0] = t4.x; xv[kx][1] = t4.y; xv[kx][2] = t4.z; xv[kx][3] = t4.w;
            }
        }

        const uint32_t aStg = smb + ((s & 1) ? OFF_A1 : OFF_A0) + lane * 16;

        if (s > 0) {
            poll_cnt(grp, 128 * s);
            const char* hsrc = (const char*)g_hfrag +
                ((size_t)((s & 1) * NGRP + grp) * NCTA) * 512 + lane * 16;
            #pragma unroll
            for (int i = 0; i < 8; i++) {
                int kc = warp * 8 + i;
                cpasync16(aStg + kc * 512, hsrc + kc * 512);
            }
            cp_mbar_arrive(mbar);
        }

        // x-part GEMM (regs only; overlaps cp.async flight)
        #pragma unroll
        for (int kx = 0; kx < NCH_X; kx++) {
            float* d0 = (kx & 1) ? accB[0] : accA[0];
            float* d1 = (kx & 1) ? accB[1] : accA[1];
            mma_f16(d0, xv[kx], bfr[NCH_H + kx]);
            mma_f16(d1, xv[kx], bfr[NCH_H + kx] + 2);
        }

        // h-part GEMM (after mbarrier parity wait; no syncthreads)
        if (s > 0) {
            mbar_wait(mbar, (s - 1) & 1);
            #pragma unroll
            for (int kc = 0; kc < NCH_H; kc++) {
                unsigned av[4];
                lds128(av, aStg + kc * 512);
                float* d0 = (kc & 1) ? accB[0] : accA[0];
                float* d1 = (kc & 1) ? accB[1] : accA[1];
                mma_f16(d0, av, bfr[kc]);
                mma_f16(d1, av, bfr[kc] + 2);
            }
        }

        // register epilogue: combine chains, gate exchange, packed h store
        char* hdst = (char*)g_hfrag +
            ((size_t)(((s + 1) & 1) * NGRP + grp) * NCTA + gc) * 512;
        #pragma unroll
        for (int t = 0; t < 2; t++) {
            float a0 = accA[t][0] + accB[t][0];
            float a1 = accA[t][1] + accB[t][1];
            float a2 = accA[t][2] + accB[t][2];
            float a3 = accA[t][3] + accB[t][3];
            float e0 = __shfl_xor_sync(0xffffffffu, a0, 1);
            float e1 = __shfl_xor_sync(0xffffffffu, a1, 1);
            float e2 = __shfl_xor_sync(0xffffffffu, a2, 1);
            float e3 = __shfl_xor_sync(0xffffffffu, a3, 1);
            float gi, gf, gg, go;
            int bidx;
            if ((lane & 1) == 0) {
                gi = a0; gf = a1; gg = e0; go = e1; bidx = r;
            } else {
                gi = e2; gf = e3; gg = a2; go = a3; bidx = r + 8;
            }
            float i_ = fsig(gi), f_ = fsig(gf), g_ = ftanh(gg), o_ = fsig(go);
            float& cc = t ? c1 : c0;
            cc = f_ * cc + i_ * g_;
            float h = o_ * ftanh(cc);
            // pack two fp16 (q=0 lo, q=1 hi) into one b32 word
            unsigned hb = (unsigned)__half_as_ushort(__float2half(h));
            unsigned ob = __shfl_xor_sync(0xffffffffu, hb, 2);
            if (q == 0) {
                unsigned word = hb | (ob << 16);
                int lt = ((bidx & 7) << 2) | lt_c | t;
                int jt = jt_c | (bidx >> 3);
                *(unsigned*)(hdst + lt * 16 + jt * 4) = word;
            }
            if (s == SEQ - 1) g_hfin[b0 + bidx][h0 + warp * 4 + t * 2 + q] = h;
        }
        if (lane == 0) release_inc(grp);
    }

    // FC head: one CTA per group, exact fp32 h
    if (gc == 0) {
        poll_cnt(grp, 128 * SEQ);
        int b = tid >> 3, l8 = tid & 7;
        float a7[7] = {0.f, 0.f, 0.f, 0.f, 0.f, 0.f, 0.f};
        for (int it = 0; it < HDIM / 8; it++) {
            int k = l8 + it * 8;
            float hv;
            asm volatile("ld.relaxed.gpu.global.f32 %0, [%1];"
                         : "=f"(hv) : "l"(&g_hfin[b0 + b][k]));
            #pragma unroll
            for (int o = 0; o < 7; o++) a7[o] += hv * fc_w[k * 7 + o];
        }
        #pragma unroll
        for (int o = 0; o < 7; o++) {
            a7[o] += __shfl_xor_sync(0xffffffffu, a7[o], 4);
            a7[o] += __shfl_xor_sync(0xffffffffu, a7[o], 2);
            a7[o] += __shfl_xor_sync(0xffffffffu, a7[o], 1);
        }
        if (l8 == 0)
            #pragma unroll
            for (int o = 0; o < 7; o++) out[(b0 + b) * 7 + o] = a7[o] + fc_b[o];
    }
}

extern "C" void kernel_launch(void* const* d_in, const int* in_sizes, int n_in,
                              void* d_out, int out_size)
{
    (void)in_sizes; (void)n_in; (void)out_size;
    const float* x    = (const float*)d_in[0];
    const float* W    = (const float*)d_in[1];
    const float* U    = (const float*)d_in[2];
    const float* bias = (const float*)d_in[3];
    const float* fc_w = (const float*)d_in[4];
    const float* fc_b = (const float*)d_in[5];

    cudaFuncSetAttribute(lstm_kernel,
                         cudaFuncAttributeMaxDynamicSharedMemorySize, SMEM_SZ);
    xsplit_kernel<<<BATCH * SEQ * IDIM / 1024, 256>>>(x);
    lstm_kernel<<<NGRP * NCTA, THREADS, SMEM_SZ>>>(W, U, bias, fc_w, fc_b, (float*)d_out);
}